// round 16
// baseline (speedup 1.0000x reference)
#include <cuda_runtime.h>

// LFQ quantizer, v11 — SPARSE formulation.
//
// T=0.01 saturates the softmax: probs_j = prod_d sigmoid(400*s_d(j)*x_d), and
// sigmoid(400|x|) == 1.0f exactly in fp32 once 400|x| >= ~17 (e^{-u} < ulp).
// With cutoff AU_CUT=30, a dim is "active" iff 400|x_d| < 30 (P~6%); probs are
// nonzero only on the 2^a codes spanned by active dims (E[2^a] ~ 2.3/row).
// Kept probs are bit-identical to the dense product; dropped mass < 1.5e-9/row.
//
// One kernel: thread-per-row sparse scatter into g_avg[16384] via RED.F32,
// then fence/ticket tail computes codebook entropy + scalars and resets state.

#define NROW    4096
#define NDIM    14
#define NCODES  16384
#define NT      256
#define GRID    16          // GRID*NT == NROW (one thread per row)
#define AU_CUT  30.0f

// scratch (__device__ globals; zero-init at load; reset by tail each call)
__device__ float g_avg[NCODES];
__device__ float g_pH[GRID];
__device__ float g_pC[GRID];
__device__ unsigned int g_ticket;

__global__ __launch_bounds__(NT) void lfq_kernel(const float* __restrict__ x,
                                                 float* __restrict__ out)
{
    __shared__ float SX[NT * NDIM];        // staged x; reused as tail reduce buf
    __shared__ float SQ[NT][NDIM + 1];     // q_plus = sigmoid(400*x) per (row,dim)
    __shared__ float sWH[8], sWC[8];
    __shared__ int sh_last;

    const int t = threadIdx.x;
    const int b = blockIdx.x;
    const int row = b * NT + t;

    // coalesced stage of this block's 256 rows
    const float* xb = x + b * NT * NDIM;
#pragma unroll
    for (int k = 0; k < NDIM; k++)
        SX[t + k * NT] = xb[t + k * NT];
    __syncthreads();

    // ---- per-row scalar pass: quantized, index, H, C, q table, active mask ----
    float h = 0.f, c = 0.f;
    int j_in = 0;          // little-endian code bits fixed by inactive dims
    int amask = 0;         // active-dim mask
    int idx_be = 0;        // big-endian packed index (reference convention)
#pragma unroll
    for (int d = 0; d < NDIM; d++) {
        const float xv = SX[t * NDIM + d];
        const int pos = xv > 0.f ? 1 : 0;
        const float au = fabsf(400.f * xv);
        const float e  = __expf(-au);                  // e^{-|u|}
        const float qmaj = __fdividef(1.f, 1.f + e);   // sigmoid(|u|)
        const float qmin = e * qmaj;                   // sigmoid(-|u|)
        h += log1pf(e) + qmin * au;                    // binary entropy (nats)
        const float cm = fabsf(xv) - 1.f;
        c += cm * cm;                                  // (x - sign(x))^2
        SQ[t][d] = pos ? qmaj : qmin;                  // sigmoid(400*x_d), signed
        if (au < AU_CUT)      amask |= (1 << d);
        else if (pos)         j_in  |= (1 << d);
        if (pos)              idx_be |= (1 << (13 - d));
        out[row * NDIM + d] = pos ? 1.f : -1.f;
    }
    out[NROW * NDIM + row] = (float)idx_be;

    // ---- sparse scatter: enumerate submasks of the active dims ----
    {
        unsigned sub = (unsigned)amask;
        while (true) {
            float pr = 1.f;
            unsigned rem = (unsigned)amask;
            while (rem) {
                const int d = __ffs((int)rem) - 1;
                rem &= rem - 1;
                const float q = SQ[t][d];
                pr *= ((sub >> d) & 1u) ? q : (1.f - q);
            }
            atomicAdd(&g_avg[(unsigned)j_in | sub], pr);
            if (sub == 0u) break;
            sub = (sub - 1u) & (unsigned)amask;
        }
    }

    // ---- block H/C reduction ----
#pragma unroll
    for (int off = 16; off > 0; off >>= 1) {
        h += __shfl_down_sync(0xFFFFFFFFu, h, off);
        c += __shfl_down_sync(0xFFFFFFFFu, c, off);
    }
    if ((t & 31) == 0) { sWH[t >> 5] = h; sWC[t >> 5] = c; }
    __syncthreads();
    if (t == 0) {
        float H = 0.f, C = 0.f;
#pragma unroll
        for (int w = 0; w < 8; w++) { H += sWH[w]; C += sWC[w]; }
        g_pH[b] = H; g_pC[b] = C;
    }

    // ---- ticket: release writes; last block finalizes ----
    __threadfence();
    __syncthreads();
    if (t == 0)
        sh_last = (atomicAdd(&g_ticket, 1u) == GRID - 1) ? 1 : 0;
    __syncthreads();
    if (!sh_last) return;
    __threadfence();                  // acquire side

    // ---- tail (single block): codebook entropy + scalars + state reset ----
    float term = 0.f;
#pragma unroll
    for (int k = 0; k < NCODES / NT; k++) {        // 64 codes per thread
        const int j = k * NT + t;
        const float a = g_avg[j] * (1.f / (float)NROW);
        term += a * __logf(a + 1e-5f);             // a==0 -> 0, matches ref
        g_avg[j] = 0.f;                            // reset for next replay
    }
    SX[t] = term;
    __syncthreads();
#pragma unroll
    for (int off = 128; off > 0; off >>= 1) {
        if (t < off) SX[t] += SX[t + off];
        __syncthreads();
    }
    const float sumT = SX[0];

    if (t == 0) {
        float sumH = 0.f, sumC = 0.f;
#pragma unroll
        for (int g = 0; g < GRID; g++) { sumH += g_pH[g]; sumC += g_pC[g]; }
        const float per_sample = sumH * (1.f / (float)NROW);
        const float cb_entropy = -sumT;
        float* sc = out + NROW * NDIM + NROW;
        sc[0] = per_sample;
        sc[1] = cb_entropy;
        sc[2] = per_sample - cb_entropy;
        sc[3] = sumC * (1.f / (float)(NROW * NDIM));
        g_ticket = 0u;                             // reset for next replay
    }
}

extern "C" void kernel_launch(void* const* d_in, const int* in_sizes, int n_in,
                              void* d_out, int out_size)
{
    (void)in_sizes; (void)n_in; (void)out_size;
    const float* x = (const float*)d_in[0];   // [2,2048,14] float32
    float* out = (float*)d_out;

    lfq_kernel<<<GRID, NT>>>(x, out);
}